// round 4
// baseline (speedup 1.0000x reference)
#include <cuda_runtime.h>
#include <cstdint>

// B=8192, A=26, NUM_TYPES=3, ANCHOR_DIM=31 (20 anchors, 10 vis, 1 class)
// triples = 8192*26*3 = 638976, each 31 contiguous floats.
#define ANCHOR_DIM 31
#define KSTEPS 10
#define EPSF 1e-9f

constexpr int THREADS = 128;
constexpr int WARPS = THREADS / 32;                 // 4
constexpr int TRIPLES_PER_WTILE = 32;               // one triple per lane per tile
constexpr int FPW = TRIPLES_PER_WTILE * ANCHOR_DIM; // 992 floats per array per warp-tile
constexpr int V4W = FPW / 4;                        // 248 float4s per array
constexpr int TILES_PER_WARP = 4;
constexpr int STAGES = 2;
constexpr int WARP_SMEM_FLOATS = STAGES * 2 * FPW;  // 3968 floats = 15872 B per warp
constexpr int SMEM_BYTES = WARPS * WARP_SMEM_FLOATS * 4;  // 63488 B
constexpr int MAX_BLOCKS = 2048;

__device__ double g_part0[MAX_BLOCKS];
__device__ double g_part1[MAX_BLOCKS];
__device__ double g_part2[MAX_BLOCKS];
__device__ unsigned int g_count = 0;

__device__ __forceinline__ void cp16(float* smem_dst, const float4* gsrc) {
    uint32_t s = (uint32_t)__cvta_generic_to_shared(smem_dst);
    asm volatile("cp.async.cg.shared.global [%0], [%1], 16;" :: "r"(s), "l"(gsrc));
}

__global__ void __launch_bounds__(THREADS)
loss_kernel(const float* __restrict__ pred, const float* __restrict__ gt,
            float* __restrict__ out) {
    extern __shared__ float dsm[];
    const int wid = threadIdx.x >> 5;
    const int lid = threadIdx.x & 31;

    // Warp-private buffer: stage s -> [pred FPW][gt FPW]
    float* wbuf = dsm + wid * WARP_SMEM_FLOATS;

    // This warp owns 4 consecutive 32-triple tiles (contiguous global span).
    const int gwarp = blockIdx.x * WARPS + wid;
    const size_t warp_float_base = (size_t)gwarp * TILES_PER_WARP * FPW;

    // Issue one warp-tile into a stage; one commit group per tile, per thread.
    auto issue = [&](int t, int stage) {
        float* sp = wbuf + stage * (2 * FPW);
        float* sg = sp + FPW;
        const float4* p4 = reinterpret_cast<const float4*>(pred + warp_float_base) + t * V4W;
        const float4* g4 = reinterpret_cast<const float4*>(gt + warp_float_base) + t * V4W;
        for (int i = lid; i < V4W; i += 32) {
            cp16(sp + 4 * i, p4 + i);
            cp16(sg + 4 * i, g4 + i);
        }
        asm volatile("cp.async.commit_group;" ::: "memory");
    };

    issue(0, 0);
    issue(1, 1);

    float s0 = 0.0f, s1 = 0.0f, s2 = 0.0f;

#pragma unroll
    for (int k = 0; k < TILES_PER_WARP; k++) {
        const int stage = k & 1;
        if (k == TILES_PER_WARP - 1) {
            asm volatile("cp.async.wait_group 0;" ::: "memory");
        } else {
            asm volatile("cp.async.wait_group 1;" ::: "memory");
        }
        __syncwarp();  // all lanes' groups done -> cross-lane smem data valid

        // One triple per lane; stride 31 coprime with 32 banks -> conflict-free.
        const float* tp = wbuf + stage * (2 * FPW) + lid * ANCHOR_DIM;
        const float* tg = tp + FPW;

        // BCE in base-2 on the MUFU pipe; convert by ln2 at the very end.
        float gvis[KSTEPS];
#pragma unroll
        for (int j = 0; j < KSTEPS; j++) {
            float g = tg[2 * KSTEPS + j];
            float p = tp[2 * KSTEPS + j];
            gvis[j] = g;
            s0 += g * __log2f(p + EPSF) + (1.0f - g + EPSF) * __log2f(1.0f - p + EPSF);
        }
        float gcls = tg[3 * KSTEPS];
        float pcls = tp[3 * KSTEPS];
        s1 += gcls * __log2f(pcls + EPSF) + (1.0f - gcls) * __log2f(1.0f - pcls + EPSF);

        // |c*d| == |c|*|d| exactly; c = gcls*gvis >= 0.
#pragma unroll
        for (int j = 0; j < KSTEPS; j++) {
            float c = gcls * gvis[j];
            s2 += c * (fabsf(tp[j] - tg[j]) + fabsf(tp[KSTEPS + j] - tg[KSTEPS + j]));
        }

        __syncwarp();  // all lanes done reading this stage before refill
        if (k + 2 < TILES_PER_WARP) issue(k + 2, stage);
    }

    // Block reduction (cold path).
#pragma unroll
    for (int o = 16; o > 0; o >>= 1) {
        s0 += __shfl_xor_sync(0xffffffffu, s0, o);
        s1 += __shfl_xor_sync(0xffffffffu, s1, o);
        s2 += __shfl_xor_sync(0xffffffffu, s2, o);
    }
    __shared__ float red[3][WARPS];
    if (lid == 0) { red[0][wid] = s0; red[1][wid] = s1; red[2][wid] = s2; }
    __syncthreads();

    __shared__ bool is_last;
    if (threadIdx.x == 0) {
        float a0 = 0.0f, a1 = 0.0f, a2 = 0.0f;
#pragma unroll
        for (int w = 0; w < WARPS; w++) { a0 += red[0][w]; a1 += red[1][w]; a2 += red[2][w]; }
        g_part0[blockIdx.x] = (double)a0;
        g_part1[blockIdx.x] = (double)a1;
        g_part2[blockIdx.x] = (double)a2;
        __threadfence();
        unsigned int c = atomicAdd(&g_count, 1u);
        is_last = (c == gridDim.x - 1);
    }
    __syncthreads();
    if (!is_last) return;

    // Last block folds all per-block partials and writes the 4 outputs.
    __threadfence();
    double a0 = 0.0, a1 = 0.0, a2 = 0.0;
    for (int i = threadIdx.x; i < gridDim.x; i += THREADS) {
        a0 += g_part0[i];
        a1 += g_part1[i];
        a2 += g_part2[i];
    }
#pragma unroll
    for (int o = 16; o > 0; o >>= 1) {
        a0 += __shfl_xor_sync(0xffffffffu, a0, o);
        a1 += __shfl_xor_sync(0xffffffffu, a1, o);
        a2 += __shfl_xor_sync(0xffffffffu, a2, o);
    }
    __shared__ double dred[3][WARPS];
    if (lid == 0) { dred[0][wid] = a0; dred[1][wid] = a1; dred[2][wid] = a2; }
    __syncthreads();
    if (threadIdx.x == 0) {
        double t0 = 0.0, t1 = 0.0, t2 = 0.0;
#pragma unroll
        for (int w = 0; w < WARPS; w++) { t0 += dred[0][w]; t1 += dred[1][w]; t2 += dred[2][w]; }
        const double LN2 = 0.6931471805599453;
        float l0 = (float)(-t0 * LN2 / (double)KSTEPS);
        float l1 = (float)(-t1 * LN2);
        float l2 = (float)(t2);
        out[0] = l0 + l1 + l2;
        out[1] = l0;
        out[2] = l1;
        out[3] = l2;
        g_count = 0;  // self-reset -> deterministic across graph replays
    }
}

extern "C" void kernel_launch(void* const* d_in, const int* in_sizes, int n_in,
                              void* d_out, int out_size) {
    const float* pred = (const float*)d_in[0];
    const float* gt   = (const float*)d_in[1];
    // d_in[2..5] (hcam/pitch) are unused by the reference.

    int total_floats = in_sizes[0];             // 19,808,256
    int triples = total_floats / ANCHOR_DIM;    // 638,976
    int blocks = triples / (WARPS * TRIPLES_PER_WTILE * TILES_PER_WARP);  // 1248 exact

    cudaFuncSetAttribute(loss_kernel, cudaFuncAttributeMaxDynamicSharedMemorySize,
                         SMEM_BYTES);
    loss_kernel<<<blocks, THREADS, SMEM_BYTES>>>(pred, gt, (float*)d_out);
}

// round 5
// speedup vs baseline: 1.1135x; 1.1135x over previous
#include <cuda_runtime.h>
#include <cstdint>

// B=8192, A=26, NUM_TYPES=3, ANCHOR_DIM=31 (20 anchors, 10 vis, 1 class)
// triples = 8192*26*3 = 638976, each 31 contiguous floats.
#define ANCHOR_DIM 31
#define KSTEPS 10
#define EPSF 1e-9f

constexpr int THREADS = 128;
constexpr int WARPS = THREADS / 32;                 // 4
constexpr int TRIPLES_PER_WTILE = 32;               // one triple per lane
constexpr int FPW = TRIPLES_PER_WTILE * ANCHOR_DIM; // 992 floats per array per warp-tile
constexpr int V4W = FPW / 4;                        // 248 float4s per array
constexpr int STAGES = 2;
constexpr int WARP_SMEM_FLOATS = STAGES * 2 * FPW;  // 3968 floats = 15872 B / warp
constexpr int SMEM_BYTES = WARPS * WARP_SMEM_FLOATS * 4;  // 63488 B
constexpr int GRID = 456;                            // 152 SMs x 3 resident = 1 wave

__device__ double g_part0[GRID];
__device__ double g_part1[GRID];
__device__ double g_part2[GRID];
__device__ unsigned int g_count = 0;

__device__ __forceinline__ void cp16(float* smem_dst, const float4* gsrc) {
    uint32_t s = (uint32_t)__cvta_generic_to_shared(smem_dst);
    asm volatile("cp.async.cg.shared.global [%0], [%1], 16;" :: "r"(s), "l"(gsrc));
}

__global__ void __launch_bounds__(THREADS)
loss_kernel(const float* __restrict__ pred, const float* __restrict__ gt,
            float* __restrict__ out, int num_tiles) {
    extern __shared__ float dsm[];
    const int wid = threadIdx.x >> 5;
    const int lid = threadIdx.x & 31;

    float* wbuf = dsm + wid * WARP_SMEM_FLOATS;      // warp-private, 2 stages

    const int gwarp = blockIdx.x * WARPS + wid;      // 0..1823
    const int wstride = GRID * WARPS;                // 1824

    // Issue warp-tile t (global index) into stage; one cp.async group per thread.
    auto issue = [&](int t, int stage) {
        float* sp = wbuf + stage * (2 * FPW);
        float* sg = sp + FPW;
        const float4* p4 = reinterpret_cast<const float4*>(pred) + (size_t)t * V4W;
        const float4* g4 = reinterpret_cast<const float4*>(gt) + (size_t)t * V4W;
#pragma unroll 8
        for (int i = lid; i < V4W; i += 32) {
            cp16(sp + 4 * i, p4 + i);
            cp16(sg + 4 * i, g4 + i);
        }
        asm volatile("cp.async.commit_group;" ::: "memory");
    };

    float s0 = 0.0f, s1 = 0.0f, s2 = 0.0f;

    // Persistent grid-strided tile stream with 2-stage warp-private pipeline.
    // Fill:
    if (gwarp < num_tiles)            issue(gwarp, 0);
    if (gwarp + wstride < num_tiles)  issue(gwarp + wstride, 1);

    int stage = 0;
    for (int tile = gwarp; tile < num_tiles; tile += wstride) {
        const bool has_next = (tile + wstride < num_tiles);
        if (has_next) {
            asm volatile("cp.async.wait_group 1;" ::: "memory");
        } else {
            asm volatile("cp.async.wait_group 0;" ::: "memory");
        }
        __syncwarp();

        // One triple per lane; stride 31 coprime with 32 banks -> conflict-free.
        const float* tp = wbuf + stage * (2 * FPW) + lid * ANCHOR_DIM;
        const float* tg = tp + FPW;

        // BCE in base-2 on the MUFU pipe; scale by ln2 once at the end.
        float gvis[KSTEPS];
#pragma unroll
        for (int j = 0; j < KSTEPS; j++) {
            float g = tg[2 * KSTEPS + j];
            float p = tp[2 * KSTEPS + j];
            gvis[j] = g;
            s0 += g * __log2f(p + EPSF) + (1.0f - g + EPSF) * __log2f(1.0f - p + EPSF);
        }
        float gcls = tg[3 * KSTEPS];
        float pcls = tp[3 * KSTEPS];
        s1 += gcls * __log2f(pcls + EPSF) + (1.0f - gcls) * __log2f(1.0f - pcls + EPSF);

        // |c*d| == |c|*|d| exactly; c = gcls*gvis >= 0.
#pragma unroll
        for (int j = 0; j < KSTEPS; j++) {
            float c = gcls * gvis[j];
            s2 += c * (fabsf(tp[j] - tg[j]) + fabsf(tp[KSTEPS + j] - tg[KSTEPS + j]));
        }

        __syncwarp();  // all lanes done reading before the refill overwrites
        if (has_next && tile + 2 * wstride < num_tiles) issue(tile + 2 * wstride, stage);
        stage ^= 1;
    }

    // Block reduction (cold path).
#pragma unroll
    for (int o = 16; o > 0; o >>= 1) {
        s0 += __shfl_xor_sync(0xffffffffu, s0, o);
        s1 += __shfl_xor_sync(0xffffffffu, s1, o);
        s2 += __shfl_xor_sync(0xffffffffu, s2, o);
    }
    __shared__ float red[3][WARPS];
    if (lid == 0) { red[0][wid] = s0; red[1][wid] = s1; red[2][wid] = s2; }
    __syncthreads();

    __shared__ bool is_last;
    if (threadIdx.x == 0) {
        float a0 = 0.0f, a1 = 0.0f, a2 = 0.0f;
#pragma unroll
        for (int w = 0; w < WARPS; w++) { a0 += red[0][w]; a1 += red[1][w]; a2 += red[2][w]; }
        g_part0[blockIdx.x] = (double)a0;
        g_part1[blockIdx.x] = (double)a1;
        g_part2[blockIdx.x] = (double)a2;
        __threadfence();
        unsigned int c = atomicAdd(&g_count, 1u);
        is_last = (c == gridDim.x - 1);
    }
    __syncthreads();
    if (!is_last) return;

    // Last block folds all per-block partials and writes the 4 outputs.
    __threadfence();
    double a0 = 0.0, a1 = 0.0, a2 = 0.0;
    for (int i = threadIdx.x; i < gridDim.x; i += THREADS) {
        a0 += g_part0[i];
        a1 += g_part1[i];
        a2 += g_part2[i];
    }
#pragma unroll
    for (int o = 16; o > 0; o >>= 1) {
        a0 += __shfl_xor_sync(0xffffffffu, a0, o);
        a1 += __shfl_xor_sync(0xffffffffu, a1, o);
        a2 += __shfl_xor_sync(0xffffffffu, a2, o);
    }
    __shared__ double dred[3][WARPS];
    if (lid == 0) { dred[0][wid] = a0; dred[1][wid] = a1; dred[2][wid] = a2; }
    __syncthreads();
    if (threadIdx.x == 0) {
        double t0 = 0.0, t1 = 0.0, t2 = 0.0;
#pragma unroll
        for (int w = 0; w < WARPS; w++) { t0 += dred[0][w]; t1 += dred[1][w]; t2 += dred[2][w]; }
        const double LN2 = 0.6931471805599453;
        float l0 = (float)(-t0 * LN2 / (double)KSTEPS);
        float l1 = (float)(-t1 * LN2);
        float l2 = (float)(t2);
        out[0] = l0 + l1 + l2;
        out[1] = l0;
        out[2] = l1;
        out[3] = l2;
        g_count = 0;  // self-reset -> deterministic across graph replays
    }
}

extern "C" void kernel_launch(void* const* d_in, const int* in_sizes, int n_in,
                              void* d_out, int out_size) {
    const float* pred = (const float*)d_in[0];
    const float* gt   = (const float*)d_in[1];
    // d_in[2..5] (hcam/pitch) are unused by the reference.

    int total_floats = in_sizes[0];                       // 19,808,256
    int num_tiles = total_floats / (ANCHOR_DIM * TRIPLES_PER_WTILE);  // 19,968

    cudaFuncSetAttribute(loss_kernel, cudaFuncAttributeMaxDynamicSharedMemorySize,
                         SMEM_BYTES);
    loss_kernel<<<GRID, THREADS, SMEM_BYTES>>>(pred, gt, (float*)d_out, num_tiles);
}

// round 6
// speedup vs baseline: 1.1221x; 1.0077x over previous
#include <cuda_runtime.h>
#include <cstdint>

// B=8192, A=26, NUM_TYPES=3, ANCHOR_DIM=31 (20 anchors, 10 vis, 1 class)
// triples = 8192*26*3 = 638976, each 31 contiguous floats.
// Layout per triple: x[0..9], z[10..19], vis[20..29], class[30].
#define ANCHOR_DIM 31
#define KSTEPS 10
#define EPSF 1e-9f

constexpr int THREADS = 128;
constexpr int WARPS = THREADS / 32;                 // 4
constexpr int TRIPLES_PER_WTILE = 16;               // two lanes per triple
constexpr int FPW = TRIPLES_PER_WTILE * ANCHOR_DIM; // 496 floats per array per warp-tile
constexpr int V4W = FPW / 4;                        // 124 float4s per array
constexpr int STAGES = 2;
constexpr int WARP_SMEM_FLOATS = STAGES * 2 * FPW;  // 1984 floats = 7936 B / warp
constexpr int SMEM_BYTES = WARPS * WARP_SMEM_FLOATS * 4;  // 31744 B / block
constexpr int BLOCKS_PER_SM = 7;                    // 7 * 31744 = 222 KB < 228 KB
constexpr int GRID = 152 * BLOCKS_PER_SM;           // 1064: exactly one wave

__device__ double g_part0[GRID];
__device__ double g_part1[GRID];
__device__ double g_part2[GRID];
__device__ unsigned int g_count = 0;

__device__ __forceinline__ void cp16(float* smem_dst, const float4* gsrc) {
    uint32_t s = (uint32_t)__cvta_generic_to_shared(smem_dst);
    asm volatile("cp.async.cg.shared.global [%0], [%1], 16;" :: "r"(s), "l"(gsrc));
}

__global__ void __launch_bounds__(THREADS, BLOCKS_PER_SM)
loss_kernel(const float* __restrict__ pred, const float* __restrict__ gt,
            float* __restrict__ out, int num_tiles) {
    extern __shared__ float dsm[];
    const int wid = threadIdx.x >> 5;
    const int lid = threadIdx.x & 31;

    float* wbuf = dsm + wid * WARP_SMEM_FLOATS;      // warp-private, 2 stages

    const int gwarp = blockIdx.x * WARPS + wid;      // 0..4255
    const int wstride = GRID * WARPS;                // 4256

    // Issue one 16-triple warp-tile into a stage (both arrays), one group/thread.
    auto issue = [&](int t, int stage) {
        float* sp = wbuf + stage * (2 * FPW);
        float* sg = sp + FPW;
        const float4* p4 = reinterpret_cast<const float4*>(pred) + (size_t)t * V4W;
        const float4* g4 = reinterpret_cast<const float4*>(gt) + (size_t)t * V4W;
#pragma unroll 4
        for (int i = lid; i < V4W; i += 32) {
            cp16(sp + 4 * i, p4 + i);
            cp16(sg + 4 * i, g4 + i);
        }
        asm volatile("cp.async.commit_group;" ::: "memory");
    };

    float s0 = 0.0f, s1 = 0.0f, s2 = 0.0f;

    // Fill pipeline.
    if (gwarp < num_tiles)            issue(gwarp, 0);
    if (gwarp + wstride < num_tiles)  issue(gwarp + wstride, 1);

    const int h = lid >> 4;          // half-id: which 5 of the 10 K-steps
    const int t = lid & 15;          // triple within tile
    const int jb = 5 * h;

    int stage = 0;
    for (int tile = gwarp; tile < num_tiles; tile += wstride) {
        const bool has_next = (tile + wstride < num_tiles);
        if (has_next) {
            asm volatile("cp.async.wait_group 1;" ::: "memory");
        } else {
            asm volatile("cp.async.wait_group 0;" ::: "memory");
        }
        __syncwarp();

        const float* tp = wbuf + stage * (2 * FPW) + t * ANCHOR_DIM;
        const float* tg = tp + FPW;

        // Each lane does 5 of the 10 K-steps of its triple.
        float gvis[5];
#pragma unroll
        for (int jj = 0; jj < 5; jj++) {
            int j = jb + jj;
            float g = tg[2 * KSTEPS + j];
            float p = tp[2 * KSTEPS + j];
            gvis[jj] = g;
            s0 += g * __log2f(p + EPSF) + (1.0f - g + EPSF) * __log2f(1.0f - p + EPSF);
        }
        float gcls = tg[3 * KSTEPS];                 // same addr both halves: broadcast
        if (h == 0) {                                // class BCE counted once per triple
            float pcls = tp[3 * KSTEPS];
            s1 += gcls * __log2f(pcls + EPSF) + (1.0f - gcls) * __log2f(1.0f - pcls + EPSF);
        }
        // |c*d| == |c|*|d| exactly; c = gcls*gvis >= 0.
#pragma unroll
        for (int jj = 0; jj < 5; jj++) {
            int j = jb + jj;
            float c = gcls * gvis[jj];
            s2 += c * (fabsf(tp[j] - tg[j]) + fabsf(tp[KSTEPS + j] - tg[KSTEPS + j]));
        }

        __syncwarp();  // all lanes done reading before the refill overwrites
        if (has_next && tile + 2 * wstride < num_tiles) issue(tile + 2 * wstride, stage);
        stage ^= 1;
    }

    // Block reduction (cold path).
#pragma unroll
    for (int o = 16; o > 0; o >>= 1) {
        s0 += __shfl_xor_sync(0xffffffffu, s0, o);
        s1 += __shfl_xor_sync(0xffffffffu, s1, o);
        s2 += __shfl_xor_sync(0xffffffffu, s2, o);
    }
    __shared__ float red[3][WARPS];
    if (lid == 0) { red[0][wid] = s0; red[1][wid] = s1; red[2][wid] = s2; }
    __syncthreads();

    __shared__ bool is_last;
    if (threadIdx.x == 0) {
        float a0 = 0.0f, a1 = 0.0f, a2 = 0.0f;
#pragma unroll
        for (int w = 0; w < WARPS; w++) { a0 += red[0][w]; a1 += red[1][w]; a2 += red[2][w]; }
        g_part0[blockIdx.x] = (double)a0;
        g_part1[blockIdx.x] = (double)a1;
        g_part2[blockIdx.x] = (double)a2;
        __threadfence();
        unsigned int c = atomicAdd(&g_count, 1u);
        is_last = (c == gridDim.x - 1);
    }
    __syncthreads();
    if (!is_last) return;

    // Last block folds all per-block partials and writes the 4 outputs.
    __threadfence();
    double a0 = 0.0, a1 = 0.0, a2 = 0.0;
    for (int i = threadIdx.x; i < gridDim.x; i += THREADS) {
        a0 += g_part0[i];
        a1 += g_part1[i];
        a2 += g_part2[i];
    }
#pragma unroll
    for (int o = 16; o > 0; o >>= 1) {
        a0 += __shfl_xor_sync(0xffffffffu, a0, o);
        a1 += __shfl_xor_sync(0xffffffffu, a1, o);
        a2 += __shfl_xor_sync(0xffffffffu, a2, o);
    }
    __shared__ double dred[3][WARPS];
    if (lid == 0) { dred[0][wid] = a0; dred[1][wid] = a1; dred[2][wid] = a2; }
    __syncthreads();
    if (threadIdx.x == 0) {
        double t0 = 0.0, t1 = 0.0, t2 = 0.0;
#pragma unroll
        for (int w = 0; w < WARPS; w++) { t0 += dred[0][w]; t1 += dred[1][w]; t2 += dred[2][w]; }
        const double LN2 = 0.6931471805599453;
        float l0 = (float)(-t0 * LN2 / (double)KSTEPS);
        float l1 = (float)(-t1 * LN2);
        float l2 = (float)(t2);
        out[0] = l0 + l1 + l2;
        out[1] = l0;
        out[2] = l1;
        out[3] = l2;
        g_count = 0;  // self-reset -> deterministic across graph replays
    }
}

extern "C" void kernel_launch(void* const* d_in, const int* in_sizes, int n_in,
                              void* d_out, int out_size) {
    const float* pred = (const float*)d_in[0];
    const float* gt   = (const float*)d_in[1];
    // d_in[2..5] (hcam/pitch) are unused by the reference.

    int total_floats = in_sizes[0];                                   // 19,808,256
    int num_tiles = total_floats / (ANCHOR_DIM * TRIPLES_PER_WTILE);  // 39,936

    cudaFuncSetAttribute(loss_kernel, cudaFuncAttributeMaxDynamicSharedMemorySize,
                         SMEM_BYTES);
    loss_kernel<<<GRID, THREADS, SMEM_BYTES>>>(pred, gt, (float*)d_out, num_tiles);
}